// round 15
// baseline (speedup 1.0000x reference)
#include <cuda_runtime.h>
#include <cuda_fp16.h>

#define NN 50000
#define NE 1600000
#define CH 64
#define INF 32
#define CAP 128           // per-node bucket capacity (mean deg = 32; P(>128) ~ e^-60)

// ---- device scratch (no allocation allowed) ----
__device__ __align__(16)  int            g_cnt[2 * NN];
__device__ __align__(16)  unsigned short g_src[2 * NN * CAP];   // 25.6MB (src < 65536)
__device__ __align__(128) float          g_A[2 * NN * CH];      // self term, fp32 (reused by layer 2)
__device__ __align__(128) __half2        g_B[2 * NN * (CH / 2)];// gathered term, fp16 (reused)
__device__ __align__(128) __half2        g_h16[2 * NN * (CH / 2)]; // layer-1 output, fp16

// ---- packed f32x2 helpers (sm_103a FFMA2 — PTX-only form) ----
typedef unsigned long long u64;
__device__ __forceinline__ u64 pack2(float x, float y) {
    u64 r; asm("mov.b64 %0, {%1,%2};" : "=l"(r) : "f"(x), "f"(y)); return r;
}
__device__ __forceinline__ void unpack2(u64 v, float& x, float& y) {
    asm("mov.b64 {%0,%1}, %2;" : "=f"(x), "=f"(y) : "l"(v));
}
__device__ __forceinline__ u64 ffma2(u64 a, u64 b, u64 c) {
    u64 d; asm("fma.rn.f32x2 %0, %1, %2, %3;" : "=l"(d) : "l"(a), "l"(b), "l"(c)); return d;
}

// ---------- init: zero bucket counters (both graphs) ----------
__global__ void k_zero() {
    int i = blockIdx.x * blockDim.x + threadIdx.x;
    if (i < 2 * NN) g_cnt[i] = 0;
}

// ---------- bucket build, ONE graph: 16 independent edge chains per thread ----------
// edge_index is int32 on device (JAX x64 disabled).
__global__ void k_scatter_g(const int* __restrict__ ei, int nb) {
    int t = blockIdx.x * blockDim.x + threadIdx.x;
    const int QH = NE / 16;
    if (t >= QH) return;
    int4 s[4], d[4];
    #pragma unroll
    for (int i = 0; i < 4; i++) {
        s[i] = ((const int4*)ei)[4 * t + i];
        d[i] = ((const int4*)(ei + NE))[4 * t + i];
    }
    #pragma unroll
    for (int i = 0; i < 4; i++) {
        int n0 = nb + d[i].x, n1 = nb + d[i].y, n2 = nb + d[i].z, n3 = nb + d[i].w;
        int p0 = atomicAdd(&g_cnt[n0], 1);
        int p1 = atomicAdd(&g_cnt[n1], 1);
        int p2 = atomicAdd(&g_cnt[n2], 1);
        int p3 = atomicAdd(&g_cnt[n3], 1);
        if (p0 < CAP) g_src[n0 * CAP + p0] = (unsigned short)s[i].x;
        if (p1 < CAP) g_src[n1 * CAP + p1] = (unsigned short)s[i].y;
        if (p2 < CAP) g_src[n2 * CAP + p2] = (unsigned short)s[i].z;
        if (p3 < CAP) g_src[n3 * CAP + p3] = (unsigned short)s[i].w;
    }
}

// ---------- mlp1, ONE graph: f32x2 GEMM. block = 128 nodes, thread = 4 nodes x 8 ch ----------
#define XS1 132
__global__ void __launch_bounds__(256) k_mlp1_g(const float* __restrict__ x,
                                                const float* __restrict__ b1,
                                                const float* __restrict__ W1,
                                                int gbase) {
    __shared__ float sWd[INF * CH];
    __shared__ float sWb[INF * CH];
    __shared__ float sX[INF * XS1];
    int tid = threadIdx.x;
    int base = blockIdx.x * 128;            // local node base within graph

    {
        float4* d4 = (float4*)sWd; float4* b4 = (float4*)sWb;
        const float4* gt = (const float4*)W1;
        const float4* gb = (const float4*)(W1 + INF * CH);
        #pragma unroll
        for (int i = 0; i < 2; i++) {
            float4 wt = gt[tid + i * 256];
            float4 wb = gb[tid + i * 256];
            d4[tid + i * 256] = make_float4(wt.x - wb.x, wt.y - wb.y,
                                            wt.z - wb.z, wt.w - wb.w);
            b4[tid + i * 256] = wb;
        }
    }
    #pragma unroll
    for (int i = 0; i < 4; i++) {
        int idx = tid + i * 256;
        int nl = base + (idx >> 3);
        int j  = idx & 7;
        if (nl < NN) {
            float4 v = *(const float4*)(x + (size_t)nl * INF + 4 * j);
            int loc = idx >> 3;
            sX[(4 * j + 0) * XS1 + loc] = v.x;
            sX[(4 * j + 1) * XS1 + loc] = v.y;
            sX[(4 * j + 2) * XS1 + loc] = v.z;
            sX[(4 * j + 3) * XS1 + loc] = v.w;
        }
    }
    __syncthreads();

    int nq = tid & 31;
    int co = tid >> 5;
    u64 a2[4][4], b2[4][4];
    #pragma unroll
    for (int j = 0; j < 4; j++) {
        float2 bv = *(const float2*)(b1 + co * 8 + 2 * j);
        u64 bp = pack2(bv.x, bv.y);
        #pragma unroll
        for (int i = 0; i < 4; i++) { a2[i][j] = bp; b2[i][j] = 0ull; }
    }

    #pragma unroll
    for (int k = 0; k < INF; k++) {
        float4 xv = *(const float4*)(sX + k * XS1 + nq * 4);
        ulonglong2 wd0 = *(const ulonglong2*)(sWd + k * CH + co * 8);
        ulonglong2 wd1 = *(const ulonglong2*)(sWd + k * CH + co * 8 + 4);
        ulonglong2 wb0 = *(const ulonglong2*)(sWb + k * CH + co * 8);
        ulonglong2 wb1 = *(const ulonglong2*)(sWb + k * CH + co * 8 + 4);
        u64 wd[4] = {wd0.x, wd0.y, wd1.x, wd1.y};
        u64 wb[4] = {wb0.x, wb0.y, wb1.x, wb1.y};
        float xs[4] = {xv.x, xv.y, xv.z, xv.w};
        #pragma unroll
        for (int i = 0; i < 4; i++) {
            u64 xp = pack2(xs[i], xs[i]);
            #pragma unroll
            for (int j = 0; j < 4; j++) {
                a2[i][j] = ffma2(xp, wd[j], a2[i][j]);
                b2[i][j] = ffma2(xp, wb[j], b2[i][j]);
            }
        }
    }

    #pragma unroll
    for (int i = 0; i < 4; i++) {
        int nl = base + nq * 4 + i;
        if (nl >= NN) continue;
        int n = gbase + nl;
        float av[8], bv[8];
        #pragma unroll
        for (int j = 0; j < 4; j++) {
            unpack2(a2[i][j], av[2 * j], av[2 * j + 1]);
            unpack2(b2[i][j], bv[2 * j], bv[2 * j + 1]);
        }
        *(float4*)(g_A + (size_t)n * CH + co * 8)     = make_float4(av[0], av[1], av[2], av[3]);
        *(float4*)(g_A + (size_t)n * CH + co * 8 + 4) = make_float4(av[4], av[5], av[6], av[7]);
        __half2 h0 = __floats2half2_rn(bv[0], bv[1]);
        __half2 h1 = __floats2half2_rn(bv[2], bv[3]);
        __half2 h2 = __floats2half2_rn(bv[4], bv[5]);
        __half2 h3 = __floats2half2_rn(bv[6], bv[7]);
        uint4 bh;
        bh.x = *(unsigned*)&h0; bh.y = *(unsigned*)&h1;
        bh.z = *(unsigned*)&h2; bh.w = *(unsigned*)&h3;
        *(uint4*)(g_B + (size_t)n * 32 + co * 4) = bh;
    }
}

// ---------- mlp2, ONE graph: f32x2 GEMM, K=64, fp16 h input. block = 64 nodes ----------
#define XS2 66
__global__ void __launch_bounds__(256) k_mlp2_g(const float* __restrict__ W2,
                                                const float* __restrict__ b2,
                                                int gbase) {
    __shared__ float sWd[CH * CH];
    __shared__ float sWb[CH * CH];
    __shared__ float sX[CH * XS2];
    int tid = threadIdx.x;
    int base = blockIdx.x * 64;             // local

    {
        float4* d4 = (float4*)sWd; float4* b4 = (float4*)sWb;
        const float4* gt = (const float4*)W2;
        const float4* gb = (const float4*)(W2 + CH * CH);
        #pragma unroll
        for (int i = 0; i < 4; i++) {
            float4 wt = gt[tid + i * 256];
            float4 wb = gb[tid + i * 256];
            d4[tid + i * 256] = make_float4(wt.x - wb.x, wt.y - wb.y,
                                            wt.z - wb.z, wt.w - wb.w);
            b4[tid + i * 256] = wb;
        }
    }
    // stage h (fp16 -> fp32), k-major: 64 nodes x 8 chunks of 8 channels
    #pragma unroll
    for (int i = 0; i < 2; i++) {
        int idx = tid + i * 256;             // 0..511
        int nl = base + (idx >> 3);
        int j  = idx & 7;                    // 8-channel chunk
        if (nl < NN) {
            uint4 v = *(const uint4*)(g_h16 + (size_t)(gbase + nl) * 32 + 4 * j);
            int loc = idx >> 3;
            float2 f0 = __half22float2(*(__half2*)&v.x);
            float2 f1 = __half22float2(*(__half2*)&v.y);
            float2 f2 = __half22float2(*(__half2*)&v.z);
            float2 f3 = __half22float2(*(__half2*)&v.w);
            sX[(8 * j + 0) * XS2 + loc] = f0.x;
            sX[(8 * j + 1) * XS2 + loc] = f0.y;
            sX[(8 * j + 2) * XS2 + loc] = f1.x;
            sX[(8 * j + 3) * XS2 + loc] = f1.y;
            sX[(8 * j + 4) * XS2 + loc] = f2.x;
            sX[(8 * j + 5) * XS2 + loc] = f2.y;
            sX[(8 * j + 6) * XS2 + loc] = f3.x;
            sX[(8 * j + 7) * XS2 + loc] = f3.y;
        }
    }
    __syncthreads();

    int np = tid & 31;
    int co = tid >> 5;
    u64 a2[2][4], b2r[2][4];
    #pragma unroll
    for (int j = 0; j < 4; j++) {
        float2 bv = *(const float2*)(b2 + co * 8 + 2 * j);
        u64 bp = pack2(bv.x, bv.y);
        a2[0][j] = bp; a2[1][j] = bp;
        b2r[0][j] = 0ull; b2r[1][j] = 0ull;
    }

    #pragma unroll
    for (int k = 0; k < CH; k++) {
        float2 xv = *(const float2*)(sX + k * XS2 + np * 2);
        ulonglong2 wd0 = *(const ulonglong2*)(sWd + k * CH + co * 8);
        ulonglong2 wd1 = *(const ulonglong2*)(sWd + k * CH + co * 8 + 4);
        ulonglong2 wb0 = *(const ulonglong2*)(sWb + k * CH + co * 8);
        ulonglong2 wb1 = *(const ulonglong2*)(sWb + k * CH + co * 8 + 4);
        u64 wd[4] = {wd0.x, wd0.y, wd1.x, wd1.y};
        u64 wb[4] = {wb0.x, wb0.y, wb1.x, wb1.y};
        float xs[2] = {xv.x, xv.y};
        #pragma unroll
        for (int i = 0; i < 2; i++) {
            u64 xp = pack2(xs[i], xs[i]);
            #pragma unroll
            for (int j = 0; j < 4; j++) {
                a2[i][j]  = ffma2(xp, wd[j], a2[i][j]);
                b2r[i][j] = ffma2(xp, wb[j], b2r[i][j]);
            }
        }
    }

    #pragma unroll
    for (int i = 0; i < 2; i++) {
        int nl = base + np * 2 + i;
        if (nl >= NN) continue;
        int n = gbase + nl;
        float av[8], bv[8];
        #pragma unroll
        for (int j = 0; j < 4; j++) {
            unpack2(a2[i][j], av[2 * j], av[2 * j + 1]);
            unpack2(b2r[i][j], bv[2 * j], bv[2 * j + 1]);
        }
        *(float4*)(g_A + (size_t)n * CH + co * 8)     = make_float4(av[0], av[1], av[2], av[3]);
        *(float4*)(g_A + (size_t)n * CH + co * 8 + 4) = make_float4(av[4], av[5], av[6], av[7]);
        __half2 h0 = __floats2half2_rn(bv[0], bv[1]);
        __half2 h1 = __floats2half2_rn(bv[2], bv[3]);
        __half2 h2 = __floats2half2_rn(bv[4], bv[5]);
        __half2 h3 = __floats2half2_rn(bv[6], bv[7]);
        uint4 bh;
        bh.x = *(unsigned*)&h0; bh.y = *(unsigned*)&h1;
        bh.z = *(unsigned*)&h2; bh.w = *(unsigned*)&h3;
        *(uint4*)(g_B + (size_t)n * 32 + co * 4) = bh;
    }
}

// ---------- edge conv, ONE graph: warp per node, 16 edges/iter ----------
// out[n][c] = max(0, A[n][c] + max_e B[src_e][c])
__device__ __forceinline__ void hmax4(__half2 m[4], uint4 v) {
    m[0] = __hmax2(m[0], *(__half2*)&v.x);
    m[1] = __hmax2(m[1], *(__half2*)&v.y);
    m[2] = __hmax2(m[2], *(__half2*)&v.z);
    m[3] = __hmax2(m[3], *(__half2*)&v.w);
}

// gather-max for node n (q = channel group, sub = edge slot); result in m[4]
__device__ __forceinline__ void conv_gather(int n, int sbase, int q, int sub, __half2 m[4]) {
    int cnt = g_cnt[n];
    if (cnt > CAP) cnt = CAP;
    const unsigned short* sp = g_src + (size_t)n * CAP;

    unsigned ninf = 0xFC00FC00u;
    m[0] = *(__half2*)&ninf; m[1] = m[0]; m[2] = m[0]; m[3] = m[0];

    int e = 0;
    for (; e + 16 <= cnt; e += 16) {
        ushort4 s4 = *(const ushort4*)(sp + e + 4 * sub);
        uint4 v0 = *(const uint4*)(g_B + (size_t)(s4.x + sbase) * 32 + 4 * q);
        uint4 v1 = *(const uint4*)(g_B + (size_t)(s4.y + sbase) * 32 + 4 * q);
        uint4 v2 = *(const uint4*)(g_B + (size_t)(s4.z + sbase) * 32 + 4 * q);
        uint4 v3 = *(const uint4*)(g_B + (size_t)(s4.w + sbase) * 32 + 4 * q);
        hmax4(m, v0); hmax4(m, v1); hmax4(m, v2); hmax4(m, v3);
    }
    for (; e < cnt; e += 4) {
        int ii = e + sub;
        if (ii < cnt) {
            int s = sp[ii] + sbase;
            uint4 v = *(const uint4*)(g_B + (size_t)s * 32 + 4 * q);
            hmax4(m, v);
        }
    }
    #pragma unroll
    for (int d = 8; d <= 16; d <<= 1) {
        #pragma unroll
        for (int r = 0; r < 4; r++) {
            unsigned t = __shfl_xor_sync(0xffffffffu, *(unsigned*)&m[r], d);
            m[r] = __hmax2(m[r], *(__half2*)&t);
        }
    }
}

// layer-1 conv: writes h (fp16) to g_h16
__global__ void __launch_bounds__(256) k_conv_h_g(int gbase) {
    int nl = (blockIdx.x * blockDim.x + threadIdx.x) >> 5;
    if (nl >= NN) return;
    int lane = threadIdx.x & 31;
    int q = lane & 7, sub = lane >> 3;
    int n = gbase + nl;
    __half2 m[4];
    conv_gather(n, gbase, q, sub, m);
    if (sub == 0) {
        float4 a0 = *(const float4*)(g_A + (size_t)n * CH + 8 * q);
        float4 a1 = *(const float4*)(g_A + (size_t)n * CH + 8 * q + 4);
        float2 f0 = __half22float2(m[0]);
        float2 f1 = __half22float2(m[1]);
        float2 f2 = __half22float2(m[2]);
        float2 f3 = __half22float2(m[3]);
        __half2 h0 = __floats2half2_rn(fmaxf(0.f, a0.x + f0.x), fmaxf(0.f, a0.y + f0.y));
        __half2 h1 = __floats2half2_rn(fmaxf(0.f, a0.z + f1.x), fmaxf(0.f, a0.w + f1.y));
        __half2 h2 = __floats2half2_rn(fmaxf(0.f, a1.x + f2.x), fmaxf(0.f, a1.y + f2.y));
        __half2 h3 = __floats2half2_rn(fmaxf(0.f, a1.z + f3.x), fmaxf(0.f, a1.w + f3.y));
        uint4 hh;
        hh.x = *(unsigned*)&h0; hh.y = *(unsigned*)&h1;
        hh.z = *(unsigned*)&h2; hh.w = *(unsigned*)&h3;
        *(uint4*)(g_h16 + (size_t)n * 32 + 4 * q) = hh;
    }
}

// layer-2 conv: writes fp32 output
__global__ void __launch_bounds__(256) k_conv_out_g(float* __restrict__ out, int gbase) {
    int nl = (blockIdx.x * blockDim.x + threadIdx.x) >> 5;
    if (nl >= NN) return;
    int lane = threadIdx.x & 31;
    int q = lane & 7, sub = lane >> 3;
    int n = gbase + nl;
    __half2 m[4];
    conv_gather(n, gbase, q, sub, m);
    if (sub == 0) {
        float4 a0 = *(const float4*)(g_A + (size_t)n * CH + 8 * q);
        float4 a1 = *(const float4*)(g_A + (size_t)n * CH + 8 * q + 4);
        float2 f0 = __half22float2(m[0]);
        float2 f1 = __half22float2(m[1]);
        float2 f2 = __half22float2(m[2]);
        float2 f3 = __half22float2(m[3]);
        float4 r0, r1;
        r0.x = fmaxf(0.f, a0.x + f0.x); r0.y = fmaxf(0.f, a0.y + f0.y);
        r0.z = fmaxf(0.f, a0.z + f1.x); r0.w = fmaxf(0.f, a0.w + f1.y);
        r1.x = fmaxf(0.f, a1.x + f2.x); r1.y = fmaxf(0.f, a1.y + f2.y);
        r1.z = fmaxf(0.f, a1.z + f3.x); r1.w = fmaxf(0.f, a1.w + f3.y);
        *(float4*)(out + (size_t)n * CH + 8 * q)     = r0;
        *(float4*)(out + (size_t)n * CH + 8 * q + 4) = r1;
    }
}

extern "C" void kernel_launch(void* const* d_in, const int* in_sizes, int n_in,
                              void* d_out, int out_size) {
    const float* x1  = (const float*)d_in[0];
    const int*   ei1 = (const int*)d_in[1];    // int32 (JAX x64 disabled)
    const float* x2  = (const float*)d_in[2];
    const int*   ei2 = (const int*)d_in[3];
    const float* W1  = (const float*)d_in[4];
    const float* b1  = (const float*)d_in[5];
    // d_in[6] = prelu_a: unused — PReLU input is provably >= 0 (identity branch)
    const float* W2  = (const float*)d_in[7];
    const float* b2  = (const float*)d_in[8];
    float* out = (float*)d_out;

    const int TB = 256;
    const int gI  = (2 * NN + TB - 1) / TB;
    const int gE  = ((NE / 16) + TB - 1) / TB;    // 16 edges/thread, one graph
    const int gM1 = (NN + 127) / 128;
    const int gM2 = (NN + 63) / 64;
    const int gW  = (NN * 32 + TB - 1) / TB;

    static cudaStream_t sA2 = nullptr, sB = nullptr, sB2 = nullptr;
    static cudaEvent_t evFork = nullptr, evA2 = nullptr, evB2 = nullptr, evJoinB = nullptr;
    if (!sB) {
        cudaStreamCreateWithFlags(&sA2, cudaStreamNonBlocking);
        cudaStreamCreateWithFlags(&sB,  cudaStreamNonBlocking);
        cudaStreamCreateWithFlags(&sB2, cudaStreamNonBlocking);
        cudaEventCreateWithFlags(&evFork, cudaEventDisableTiming);
        cudaEventCreateWithFlags(&evA2, cudaEventDisableTiming);
        cudaEventCreateWithFlags(&evB2, cudaEventDisableTiming);
        cudaEventCreateWithFlags(&evJoinB, cudaEventDisableTiming);
    }

    // shared init, then fork two independent per-graph chains,
    // each with scatter || mlp1 inner parallelism
    k_zero<<<gI, TB>>>();
    cudaEventRecord(evFork, 0);
    cudaStreamWaitEvent(sA2, evFork, 0);
    cudaStreamWaitEvent(sB,  evFork, 0);
    cudaStreamWaitEvent(sB2, evFork, 0);

    // chain A (graph 1): stream0 = scatter path, sA2 = mlp1 path
    k_mlp1_g<<<gM1, TB, 0, sA2>>>(x1, b1, W1, 0);
    cudaEventRecord(evA2, sA2);
    k_scatter_g<<<gE, TB>>>(ei1, 0);
    cudaStreamWaitEvent(0, evA2, 0);
    k_conv_h_g<<<gW, TB>>>(0);
    k_mlp2_g<<<gM2, TB>>>(W2, b2, 0);
    k_conv_out_g<<<gW, TB>>>(out, 0);

    // chain B (graph 2): sB = scatter path, sB2 = mlp1 path
    k_mlp1_g<<<gM1, TB, 0, sB2>>>(x2, b1, W1, NN);
    cudaEventRecord(evB2, sB2);
    k_scatter_g<<<gE, TB, 0, sB>>>(ei2, NN);
    cudaStreamWaitEvent(sB, evB2, 0);
    k_conv_h_g<<<gW, TB, 0, sB>>>(NN);
    k_mlp2_g<<<gM2, TB, 0, sB>>>(W2, b2, NN);
    k_conv_out_g<<<gW, TB, 0, sB>>>(out, NN);

    // join
    cudaEventRecord(evJoinB, sB);
    cudaStreamWaitEvent(0, evJoinB, 0);
}

// round 16
// speedup vs baseline: 1.0592x; 1.0592x over previous
#include <cuda_runtime.h>
#include <cuda_fp16.h>

#define NN 50000
#define NE 1600000
#define CH 64
#define INF 32
#define CAP 128           // per-node bucket capacity (mean deg = 32; P(>128) ~ e^-60)

// ---- device scratch (no allocation allowed) ----
__device__ __align__(16)  int            g_cnt[2 * NN];
__device__ __align__(16)  unsigned short g_src[2 * NN * CAP];   // 25.6MB (src < 65536)
__device__ __align__(128) float          g_A[2 * NN * CH];      // self term, fp32 (reused by layer 2)
__device__ __align__(128) __half2        g_B[2 * NN * (CH / 2)];// gathered term, fp16 (reused)
__device__ __align__(128) __half2        g_h16[2 * NN * (CH / 2)]; // layer-1 output, fp16

// ---- packed f32x2 helpers (sm_103a FFMA2 — PTX-only form) ----
typedef unsigned long long u64;
__device__ __forceinline__ u64 pack2(float x, float y) {
    u64 r; asm("mov.b64 %0, {%1,%2};" : "=l"(r) : "f"(x), "f"(y)); return r;
}
__device__ __forceinline__ void unpack2(u64 v, float& x, float& y) {
    asm("mov.b64 {%0,%1}, %2;" : "=f"(x), "=f"(y) : "l"(v));
}
__device__ __forceinline__ u64 ffma2(u64 a, u64 b, u64 c) {
    u64 d; asm("fma.rn.f32x2 %0, %1, %2, %3;" : "=l"(d) : "l"(a), "l"(b), "l"(c)); return d;
}

// ---------- init: zero bucket counters (both graphs) ----------
__global__ void k_zero() {
    int i = blockIdx.x * blockDim.x + threadIdx.x;
    if (i < 2 * NN) g_cnt[i] = 0;
}

// ---------- bucket build, ONE graph: 8 independent edge chains per thread ----------
// edge_index is int32 on device (JAX x64 disabled).
__global__ void k_scatter_g(const int* __restrict__ ei, int nb) {
    int t = blockIdx.x * blockDim.x + threadIdx.x;
    const int QH = NE / 8;
    if (t >= QH) return;
    int4 sa = ((const int4*)ei)[2 * t];
    int4 sb = ((const int4*)ei)[2 * t + 1];
    int4 da = ((const int4*)(ei + NE))[2 * t];
    int4 db = ((const int4*)(ei + NE))[2 * t + 1];
    int n0 = nb + da.x, n1 = nb + da.y, n2 = nb + da.z, n3 = nb + da.w;
    int n4 = nb + db.x, n5 = nb + db.y, n6 = nb + db.z, n7 = nb + db.w;
    int p0 = atomicAdd(&g_cnt[n0], 1);
    int p1 = atomicAdd(&g_cnt[n1], 1);
    int p2 = atomicAdd(&g_cnt[n2], 1);
    int p3 = atomicAdd(&g_cnt[n3], 1);
    int p4 = atomicAdd(&g_cnt[n4], 1);
    int p5 = atomicAdd(&g_cnt[n5], 1);
    int p6 = atomicAdd(&g_cnt[n6], 1);
    int p7 = atomicAdd(&g_cnt[n7], 1);
    if (p0 < CAP) g_src[n0 * CAP + p0] = (unsigned short)sa.x;
    if (p1 < CAP) g_src[n1 * CAP + p1] = (unsigned short)sa.y;
    if (p2 < CAP) g_src[n2 * CAP + p2] = (unsigned short)sa.z;
    if (p3 < CAP) g_src[n3 * CAP + p3] = (unsigned short)sa.w;
    if (p4 < CAP) g_src[n4 * CAP + p4] = (unsigned short)sb.x;
    if (p5 < CAP) g_src[n5 * CAP + p5] = (unsigned short)sb.y;
    if (p6 < CAP) g_src[n6 * CAP + p6] = (unsigned short)sb.z;
    if (p7 < CAP) g_src[n7 * CAP + p7] = (unsigned short)sb.w;
}

// ---------- mlp1, ONE graph: f32x2 GEMM. block = 128 nodes, thread = 4 nodes x 8 ch ----------
#define XS1 132
__global__ void __launch_bounds__(256) k_mlp1_g(const float* __restrict__ x,
                                                const float* __restrict__ b1,
                                                const float* __restrict__ W1,
                                                int gbase) {
    __shared__ float sWd[INF * CH];
    __shared__ float sWb[INF * CH];
    __shared__ float sX[INF * XS1];
    int tid = threadIdx.x;
    int base = blockIdx.x * 128;            // local node base within graph

    {
        float4* d4 = (float4*)sWd; float4* b4 = (float4*)sWb;
        const float4* gt = (const float4*)W1;
        const float4* gb = (const float4*)(W1 + INF * CH);
        #pragma unroll
        for (int i = 0; i < 2; i++) {
            float4 wt = gt[tid + i * 256];
            float4 wb = gb[tid + i * 256];
            d4[tid + i * 256] = make_float4(wt.x - wb.x, wt.y - wb.y,
                                            wt.z - wb.z, wt.w - wb.w);
            b4[tid + i * 256] = wb;
        }
    }
    #pragma unroll
    for (int i = 0; i < 4; i++) {
        int idx = tid + i * 256;
        int nl = base + (idx >> 3);
        int j  = idx & 7;
        if (nl < NN) {
            float4 v = *(const float4*)(x + (size_t)nl * INF + 4 * j);
            int loc = idx >> 3;
            sX[(4 * j + 0) * XS1 + loc] = v.x;
            sX[(4 * j + 1) * XS1 + loc] = v.y;
            sX[(4 * j + 2) * XS1 + loc] = v.z;
            sX[(4 * j + 3) * XS1 + loc] = v.w;
        }
    }
    __syncthreads();

    int nq = tid & 31;
    int co = tid >> 5;
    u64 a2[4][4], b2[4][4];
    #pragma unroll
    for (int j = 0; j < 4; j++) {
        float2 bv = *(const float2*)(b1 + co * 8 + 2 * j);
        u64 bp = pack2(bv.x, bv.y);
        #pragma unroll
        for (int i = 0; i < 4; i++) { a2[i][j] = bp; b2[i][j] = 0ull; }
    }

    #pragma unroll
    for (int k = 0; k < INF; k++) {
        float4 xv = *(const float4*)(sX + k * XS1 + nq * 4);
        ulonglong2 wd0 = *(const ulonglong2*)(sWd + k * CH + co * 8);
        ulonglong2 wd1 = *(const ulonglong2*)(sWd + k * CH + co * 8 + 4);
        ulonglong2 wb0 = *(const ulonglong2*)(sWb + k * CH + co * 8);
        ulonglong2 wb1 = *(const ulonglong2*)(sWb + k * CH + co * 8 + 4);
        u64 wd[4] = {wd0.x, wd0.y, wd1.x, wd1.y};
        u64 wb[4] = {wb0.x, wb0.y, wb1.x, wb1.y};
        float xs[4] = {xv.x, xv.y, xv.z, xv.w};
        #pragma unroll
        for (int i = 0; i < 4; i++) {
            u64 xp = pack2(xs[i], xs[i]);
            #pragma unroll
            for (int j = 0; j < 4; j++) {
                a2[i][j] = ffma2(xp, wd[j], a2[i][j]);
                b2[i][j] = ffma2(xp, wb[j], b2[i][j]);
            }
        }
    }

    #pragma unroll
    for (int i = 0; i < 4; i++) {
        int nl = base + nq * 4 + i;
        if (nl >= NN) continue;
        int n = gbase + nl;
        float av[8], bv[8];
        #pragma unroll
        for (int j = 0; j < 4; j++) {
            unpack2(a2[i][j], av[2 * j], av[2 * j + 1]);
            unpack2(b2[i][j], bv[2 * j], bv[2 * j + 1]);
        }
        *(float4*)(g_A + (size_t)n * CH + co * 8)     = make_float4(av[0], av[1], av[2], av[3]);
        *(float4*)(g_A + (size_t)n * CH + co * 8 + 4) = make_float4(av[4], av[5], av[6], av[7]);
        __half2 h0 = __floats2half2_rn(bv[0], bv[1]);
        __half2 h1 = __floats2half2_rn(bv[2], bv[3]);
        __half2 h2 = __floats2half2_rn(bv[4], bv[5]);
        __half2 h3 = __floats2half2_rn(bv[6], bv[7]);
        uint4 bh;
        bh.x = *(unsigned*)&h0; bh.y = *(unsigned*)&h1;
        bh.z = *(unsigned*)&h2; bh.w = *(unsigned*)&h3;
        *(uint4*)(g_B + (size_t)n * 32 + co * 4) = bh;
    }
}

// ---------- mlp2, ONE graph: f32x2 GEMM, K=64, fp16 h input. block = 64 nodes ----------
#define XS2 66
__global__ void __launch_bounds__(256) k_mlp2_g(const float* __restrict__ W2,
                                                const float* __restrict__ b2,
                                                int gbase) {
    __shared__ float sWd[CH * CH];
    __shared__ float sWb[CH * CH];
    __shared__ float sX[CH * XS2];
    int tid = threadIdx.x;
    int base = blockIdx.x * 64;             // local

    {
        float4* d4 = (float4*)sWd; float4* b4 = (float4*)sWb;
        const float4* gt = (const float4*)W2;
        const float4* gb = (const float4*)(W2 + CH * CH);
        #pragma unroll
        for (int i = 0; i < 4; i++) {
            float4 wt = gt[tid + i * 256];
            float4 wb = gb[tid + i * 256];
            d4[tid + i * 256] = make_float4(wt.x - wb.x, wt.y - wb.y,
                                            wt.z - wb.z, wt.w - wb.w);
            b4[tid + i * 256] = wb;
        }
    }
    // stage h (fp16 -> fp32), k-major: 64 nodes x 8 chunks of 8 channels
    #pragma unroll
    for (int i = 0; i < 2; i++) {
        int idx = tid + i * 256;             // 0..511
        int nl = base + (idx >> 3);
        int j  = idx & 7;                    // 8-channel chunk
        if (nl < NN) {
            uint4 v = *(const uint4*)(g_h16 + (size_t)(gbase + nl) * 32 + 4 * j);
            int loc = idx >> 3;
            float2 f0 = __half22float2(*(__half2*)&v.x);
            float2 f1 = __half22float2(*(__half2*)&v.y);
            float2 f2 = __half22float2(*(__half2*)&v.z);
            float2 f3 = __half22float2(*(__half2*)&v.w);
            sX[(8 * j + 0) * XS2 + loc] = f0.x;
            sX[(8 * j + 1) * XS2 + loc] = f0.y;
            sX[(8 * j + 2) * XS2 + loc] = f1.x;
            sX[(8 * j + 3) * XS2 + loc] = f1.y;
            sX[(8 * j + 4) * XS2 + loc] = f2.x;
            sX[(8 * j + 5) * XS2 + loc] = f2.y;
            sX[(8 * j + 6) * XS2 + loc] = f3.x;
            sX[(8 * j + 7) * XS2 + loc] = f3.y;
        }
    }
    __syncthreads();

    int np = tid & 31;
    int co = tid >> 5;
    u64 a2[2][4], b2r[2][4];
    #pragma unroll
    for (int j = 0; j < 4; j++) {
        float2 bv = *(const float2*)(b2 + co * 8 + 2 * j);
        u64 bp = pack2(bv.x, bv.y);
        a2[0][j] = bp; a2[1][j] = bp;
        b2r[0][j] = 0ull; b2r[1][j] = 0ull;
    }

    #pragma unroll
    for (int k = 0; k < CH; k++) {
        float2 xv = *(const float2*)(sX + k * XS2 + np * 2);
        ulonglong2 wd0 = *(const ulonglong2*)(sWd + k * CH + co * 8);
        ulonglong2 wd1 = *(const ulonglong2*)(sWd + k * CH + co * 8 + 4);
        ulonglong2 wb0 = *(const ulonglong2*)(sWb + k * CH + co * 8);
        ulonglong2 wb1 = *(const ulonglong2*)(sWb + k * CH + co * 8 + 4);
        u64 wd[4] = {wd0.x, wd0.y, wd1.x, wd1.y};
        u64 wb[4] = {wb0.x, wb0.y, wb1.x, wb1.y};
        float xs[2] = {xv.x, xv.y};
        #pragma unroll
        for (int i = 0; i < 2; i++) {
            u64 xp = pack2(xs[i], xs[i]);
            #pragma unroll
            for (int j = 0; j < 4; j++) {
                a2[i][j]  = ffma2(xp, wd[j], a2[i][j]);
                b2r[i][j] = ffma2(xp, wb[j], b2r[i][j]);
            }
        }
    }

    #pragma unroll
    for (int i = 0; i < 2; i++) {
        int nl = base + np * 2 + i;
        if (nl >= NN) continue;
        int n = gbase + nl;
        float av[8], bv[8];
        #pragma unroll
        for (int j = 0; j < 4; j++) {
            unpack2(a2[i][j], av[2 * j], av[2 * j + 1]);
            unpack2(b2r[i][j], bv[2 * j], bv[2 * j + 1]);
        }
        *(float4*)(g_A + (size_t)n * CH + co * 8)     = make_float4(av[0], av[1], av[2], av[3]);
        *(float4*)(g_A + (size_t)n * CH + co * 8 + 4) = make_float4(av[4], av[5], av[6], av[7]);
        __half2 h0 = __floats2half2_rn(bv[0], bv[1]);
        __half2 h1 = __floats2half2_rn(bv[2], bv[3]);
        __half2 h2 = __floats2half2_rn(bv[4], bv[5]);
        __half2 h3 = __floats2half2_rn(bv[6], bv[7]);
        uint4 bh;
        bh.x = *(unsigned*)&h0; bh.y = *(unsigned*)&h1;
        bh.z = *(unsigned*)&h2; bh.w = *(unsigned*)&h3;
        *(uint4*)(g_B + (size_t)n * 32 + co * 4) = bh;
    }
}

// ---------- edge conv, ONE graph: warp per node, 16 edges/iter ----------
// out[n][c] = max(0, A[n][c] + max_e B[src_e][c])
__device__ __forceinline__ void hmax4(__half2 m[4], uint4 v) {
    m[0] = __hmax2(m[0], *(__half2*)&v.x);
    m[1] = __hmax2(m[1], *(__half2*)&v.y);
    m[2] = __hmax2(m[2], *(__half2*)&v.z);
    m[3] = __hmax2(m[3], *(__half2*)&v.w);
}

__device__ __forceinline__ void conv_gather(int n, int sbase, int q, int sub, __half2 m[4]) {
    int cnt = g_cnt[n];
    if (cnt > CAP) cnt = CAP;
    const unsigned short* sp = g_src + (size_t)n * CAP;

    unsigned ninf = 0xFC00FC00u;
    m[0] = *(__half2*)&ninf; m[1] = m[0]; m[2] = m[0]; m[3] = m[0];

    int e = 0;
    for (; e + 16 <= cnt; e += 16) {
        ushort4 s4 = *(const ushort4*)(sp + e + 4 * sub);
        uint4 v0 = *(const uint4*)(g_B + (size_t)(s4.x + sbase) * 32 + 4 * q);
        uint4 v1 = *(const uint4*)(g_B + (size_t)(s4.y + sbase) * 32 + 4 * q);
        uint4 v2 = *(const uint4*)(g_B + (size_t)(s4.z + sbase) * 32 + 4 * q);
        uint4 v3 = *(const uint4*)(g_B + (size_t)(s4.w + sbase) * 32 + 4 * q);
        hmax4(m, v0); hmax4(m, v1); hmax4(m, v2); hmax4(m, v3);
    }
    for (; e < cnt; e += 4) {
        int ii = e + sub;
        if (ii < cnt) {
            int s = sp[ii] + sbase;
            uint4 v = *(const uint4*)(g_B + (size_t)s * 32 + 4 * q);
            hmax4(m, v);
        }
    }
    #pragma unroll
    for (int d = 8; d <= 16; d <<= 1) {
        #pragma unroll
        for (int r = 0; r < 4; r++) {
            unsigned t = __shfl_xor_sync(0xffffffffu, *(unsigned*)&m[r], d);
            m[r] = __hmax2(m[r], *(__half2*)&t);
        }
    }
}

// layer-1 conv: writes h (fp16) to g_h16
__global__ void __launch_bounds__(256) k_conv_h_g(int gbase) {
    int nl = (blockIdx.x * blockDim.x + threadIdx.x) >> 5;
    if (nl >= NN) return;
    int lane = threadIdx.x & 31;
    int q = lane & 7, sub = lane >> 3;
    int n = gbase + nl;
    __half2 m[4];
    conv_gather(n, gbase, q, sub, m);
    if (sub == 0) {
        float4 a0 = *(const float4*)(g_A + (size_t)n * CH + 8 * q);
        float4 a1 = *(const float4*)(g_A + (size_t)n * CH + 8 * q + 4);
        float2 f0 = __half22float2(m[0]);
        float2 f1 = __half22float2(m[1]);
        float2 f2 = __half22float2(m[2]);
        float2 f3 = __half22float2(m[3]);
        __half2 h0 = __floats2half2_rn(fmaxf(0.f, a0.x + f0.x), fmaxf(0.f, a0.y + f0.y));
        __half2 h1 = __floats2half2_rn(fmaxf(0.f, a0.z + f1.x), fmaxf(0.f, a0.w + f1.y));
        __half2 h2 = __floats2half2_rn(fmaxf(0.f, a1.x + f2.x), fmaxf(0.f, a1.y + f2.y));
        __half2 h3 = __floats2half2_rn(fmaxf(0.f, a1.z + f3.x), fmaxf(0.f, a1.w + f3.y));
        uint4 hh;
        hh.x = *(unsigned*)&h0; hh.y = *(unsigned*)&h1;
        hh.z = *(unsigned*)&h2; hh.w = *(unsigned*)&h3;
        *(uint4*)(g_h16 + (size_t)n * 32 + 4 * q) = hh;
    }
}

// layer-2 conv: writes fp32 output
__global__ void __launch_bounds__(256) k_conv_out_g(float* __restrict__ out, int gbase) {
    int nl = (blockIdx.x * blockDim.x + threadIdx.x) >> 5;
    if (nl >= NN) return;
    int lane = threadIdx.x & 31;
    int q = lane & 7, sub = lane >> 3;
    int n = gbase + nl;
    __half2 m[4];
    conv_gather(n, gbase, q, sub, m);
    if (sub == 0) {
        float4 a0 = *(const float4*)(g_A + (size_t)n * CH + 8 * q);
        float4 a1 = *(const float4*)(g_A + (size_t)n * CH + 8 * q + 4);
        float2 f0 = __half22float2(m[0]);
        float2 f1 = __half22float2(m[1]);
        float2 f2 = __half22float2(m[2]);
        float2 f3 = __half22float2(m[3]);
        float4 r0, r1;
        r0.x = fmaxf(0.f, a0.x + f0.x); r0.y = fmaxf(0.f, a0.y + f0.y);
        r0.z = fmaxf(0.f, a0.z + f1.x); r0.w = fmaxf(0.f, a0.w + f1.y);
        r1.x = fmaxf(0.f, a1.x + f2.x); r1.y = fmaxf(0.f, a1.y + f2.y);
        r1.z = fmaxf(0.f, a1.z + f3.x); r1.w = fmaxf(0.f, a1.w + f3.y);
        *(float4*)(out + (size_t)n * CH + 8 * q)     = r0;
        *(float4*)(out + (size_t)n * CH + 8 * q + 4) = r1;
    }
}

extern "C" void kernel_launch(void* const* d_in, const int* in_sizes, int n_in,
                              void* d_out, int out_size) {
    const float* x1  = (const float*)d_in[0];
    const int*   ei1 = (const int*)d_in[1];    // int32 (JAX x64 disabled)
    const float* x2  = (const float*)d_in[2];
    const int*   ei2 = (const int*)d_in[3];
    const float* W1  = (const float*)d_in[4];
    const float* b1  = (const float*)d_in[5];
    // d_in[6] = prelu_a: unused — PReLU input is provably >= 0 (identity branch)
    const float* W2  = (const float*)d_in[7];
    const float* b2  = (const float*)d_in[8];
    float* out = (float*)d_out;

    const int TB = 256;
    const int gI  = (2 * NN + TB - 1) / TB;
    const int gE  = ((NE / 8) + TB - 1) / TB;     // 8 edges/thread, one graph
    const int gM1 = (NN + 127) / 128;
    const int gM2 = (NN + 63) / 64;
    const int gW  = (NN * 32 + TB - 1) / TB;

    static cudaStream_t sB = nullptr;
    static cudaEvent_t evFork = nullptr, evJoin = nullptr;
    if (!sB) {
        cudaStreamCreateWithFlags(&sB, cudaStreamNonBlocking);
        cudaEventCreateWithFlags(&evFork, cudaEventDisableTiming);
        cudaEventCreateWithFlags(&evJoin, cudaEventDisableTiming);
    }

    // shared init, then fork two fully-independent per-graph chains (R14 topology)
    k_zero<<<gI, TB>>>();
    cudaEventRecord(evFork, 0);
    cudaStreamWaitEvent(sB, evFork, 0);

    // chain A (graph 1) on default stream
    k_scatter_g<<<gE, TB>>>(ei1, 0);
    k_mlp1_g<<<gM1, TB>>>(x1, b1, W1, 0);
    k_conv_h_g<<<gW, TB>>>(0);
    k_mlp2_g<<<gM2, TB>>>(W2, b2, 0);
    k_conv_out_g<<<gW, TB>>>(out, 0);

    // chain B (graph 2) on side stream
    k_scatter_g<<<gE, TB, 0, sB>>>(ei2, NN);
    k_mlp1_g<<<gM1, TB, 0, sB>>>(x2, b1, W1, NN);
    k_conv_h_g<<<gW, TB, 0, sB>>>(NN);
    k_mlp2_g<<<gM2, TB, 0, sB>>>(W2, b2, NN);
    k_conv_out_g<<<gW, TB, 0, sB>>>(out, NN);

    // join
    cudaEventRecord(evJoin, sB);
    cudaStreamWaitEvent(0, evJoin, 0);
}

// round 17
// speedup vs baseline: 1.0658x; 1.0062x over previous
#include <cuda_runtime.h>
#include <cuda_fp16.h>

#define NN 50000
#define NE 1600000
#define CH 64
#define INF 32
#define CAP 128           // per-node bucket capacity (mean deg = 32; P(>128) ~ e^-60)

// ---- device scratch (no allocation allowed) ----
__device__ __align__(16)  int            g_cnt[2 * NN];
__device__ __align__(16)  unsigned short g_src[2 * NN * CAP];   // 25.6MB (src < 65536)
__device__ __align__(128) float          g_A[2 * NN * CH];      // self term, fp32 (reused by layer 2)
__device__ __align__(128) __half2        g_B[2 * NN * (CH / 2)];// gathered term, fp16 (reused)
__device__ __align__(128) __half2        g_h16[2 * NN * (CH / 2)]; // layer-1 output, fp16

// ---- packed f32x2 helpers (sm_103a FFMA2 — PTX-only form) ----
typedef unsigned long long u64;
__device__ __forceinline__ u64 pack2(float x, float y) {
    u64 r; asm("mov.b64 %0, {%1,%2};" : "=l"(r) : "f"(x), "f"(y)); return r;
}
__device__ __forceinline__ void unpack2(u64 v, float& x, float& y) {
    asm("mov.b64 {%0,%1}, %2;" : "=f"(x), "=f"(y) : "l"(v));
}
__device__ __forceinline__ u64 ffma2(u64 a, u64 b, u64 c) {
    u64 d; asm("fma.rn.f32x2 %0, %1, %2, %3;" : "=l"(d) : "l"(a), "l"(b), "l"(c)); return d;
}

// ---------- init: zero bucket counters (both graphs) ----------
__global__ void k_zero() {
    int i = blockIdx.x * blockDim.x + threadIdx.x;
    if (i < 2 * NN) g_cnt[i] = 0;
}

// ---------- bucket build, ONE graph: 8 independent edge chains per thread ----------
// edge_index is int32 on device (JAX x64 disabled).
__global__ void k_scatter_g(const int* __restrict__ ei, int nb) {
    int t = blockIdx.x * blockDim.x + threadIdx.x;
    const int QH = NE / 8;
    if (t >= QH) return;
    int4 sa = ((const int4*)ei)[2 * t];
    int4 sb = ((const int4*)ei)[2 * t + 1];
    int4 da = ((const int4*)(ei + NE))[2 * t];
    int4 db = ((const int4*)(ei + NE))[2 * t + 1];
    int n0 = nb + da.x, n1 = nb + da.y, n2 = nb + da.z, n3 = nb + da.w;
    int n4 = nb + db.x, n5 = nb + db.y, n6 = nb + db.z, n7 = nb + db.w;
    int p0 = atomicAdd(&g_cnt[n0], 1);
    int p1 = atomicAdd(&g_cnt[n1], 1);
    int p2 = atomicAdd(&g_cnt[n2], 1);
    int p3 = atomicAdd(&g_cnt[n3], 1);
    int p4 = atomicAdd(&g_cnt[n4], 1);
    int p5 = atomicAdd(&g_cnt[n5], 1);
    int p6 = atomicAdd(&g_cnt[n6], 1);
    int p7 = atomicAdd(&g_cnt[n7], 1);
    if (p0 < CAP) g_src[n0 * CAP + p0] = (unsigned short)sa.x;
    if (p1 < CAP) g_src[n1 * CAP + p1] = (unsigned short)sa.y;
    if (p2 < CAP) g_src[n2 * CAP + p2] = (unsigned short)sa.z;
    if (p3 < CAP) g_src[n3 * CAP + p3] = (unsigned short)sa.w;
    if (p4 < CAP) g_src[n4 * CAP + p4] = (unsigned short)sb.x;
    if (p5 < CAP) g_src[n5 * CAP + p5] = (unsigned short)sb.y;
    if (p6 < CAP) g_src[n6 * CAP + p6] = (unsigned short)sb.z;
    if (p7 < CAP) g_src[n7 * CAP + p7] = (unsigned short)sb.w;
}

// ---------- mlp1, ONE graph: f32x2 GEMM. block = 128 nodes, thread = 4 nodes x 8 ch ----------
#define XS1 132
__global__ void __launch_bounds__(256) k_mlp1_g(const float* __restrict__ x,
                                                const float* __restrict__ b1,
                                                const float* __restrict__ W1,
                                                int gbase) {
    __shared__ float sWd[INF * CH];
    __shared__ float sWb[INF * CH];
    __shared__ float sX[INF * XS1];
    int tid = threadIdx.x;
    int base = blockIdx.x * 128;            // local node base within graph

    {
        float4* d4 = (float4*)sWd; float4* b4 = (float4*)sWb;
        const float4* gt = (const float4*)W1;
        const float4* gb = (const float4*)(W1 + INF * CH);
        #pragma unroll
        for (int i = 0; i < 2; i++) {
            float4 wt = gt[tid + i * 256];
            float4 wb = gb[tid + i * 256];
            d4[tid + i * 256] = make_float4(wt.x - wb.x, wt.y - wb.y,
                                            wt.z - wb.z, wt.w - wb.w);
            b4[tid + i * 256] = wb;
        }
    }
    #pragma unroll
    for (int i = 0; i < 4; i++) {
        int idx = tid + i * 256;
        int nl = base + (idx >> 3);
        int j  = idx & 7;
        if (nl < NN) {
            float4 v = *(const float4*)(x + (size_t)nl * INF + 4 * j);
            int loc = idx >> 3;
            sX[(4 * j + 0) * XS1 + loc] = v.x;
            sX[(4 * j + 1) * XS1 + loc] = v.y;
            sX[(4 * j + 2) * XS1 + loc] = v.z;
            sX[(4 * j + 3) * XS1 + loc] = v.w;
        }
    }
    __syncthreads();

    int nq = tid & 31;
    int co = tid >> 5;
    u64 a2[4][4], b2[4][4];
    #pragma unroll
    for (int j = 0; j < 4; j++) {
        float2 bv = *(const float2*)(b1 + co * 8 + 2 * j);
        u64 bp = pack2(bv.x, bv.y);
        #pragma unroll
        for (int i = 0; i < 4; i++) { a2[i][j] = bp; b2[i][j] = 0ull; }
    }

    #pragma unroll
    for (int k = 0; k < INF; k++) {
        float4 xv = *(const float4*)(sX + k * XS1 + nq * 4);
        ulonglong2 wd0 = *(const ulonglong2*)(sWd + k * CH + co * 8);
        ulonglong2 wd1 = *(const ulonglong2*)(sWd + k * CH + co * 8 + 4);
        ulonglong2 wb0 = *(const ulonglong2*)(sWb + k * CH + co * 8);
        ulonglong2 wb1 = *(const ulonglong2*)(sWb + k * CH + co * 8 + 4);
        u64 wd[4] = {wd0.x, wd0.y, wd1.x, wd1.y};
        u64 wb[4] = {wb0.x, wb0.y, wb1.x, wb1.y};
        float xs[4] = {xv.x, xv.y, xv.z, xv.w};
        #pragma unroll
        for (int i = 0; i < 4; i++) {
            u64 xp = pack2(xs[i], xs[i]);
            #pragma unroll
            for (int j = 0; j < 4; j++) {
                a2[i][j] = ffma2(xp, wd[j], a2[i][j]);
                b2[i][j] = ffma2(xp, wb[j], b2[i][j]);
            }
        }
    }

    #pragma unroll
    for (int i = 0; i < 4; i++) {
        int nl = base + nq * 4 + i;
        if (nl >= NN) continue;
        int n = gbase + nl;
        float av[8], bv[8];
        #pragma unroll
        for (int j = 0; j < 4; j++) {
            unpack2(a2[i][j], av[2 * j], av[2 * j + 1]);
            unpack2(b2[i][j], bv[2 * j], bv[2 * j + 1]);
        }
        *(float4*)(g_A + (size_t)n * CH + co * 8)     = make_float4(av[0], av[1], av[2], av[3]);
        *(float4*)(g_A + (size_t)n * CH + co * 8 + 4) = make_float4(av[4], av[5], av[6], av[7]);
        __half2 h0 = __floats2half2_rn(bv[0], bv[1]);
        __half2 h1 = __floats2half2_rn(bv[2], bv[3]);
        __half2 h2 = __floats2half2_rn(bv[4], bv[5]);
        __half2 h3 = __floats2half2_rn(bv[6], bv[7]);
        uint4 bh;
        bh.x = *(unsigned*)&h0; bh.y = *(unsigned*)&h1;
        bh.z = *(unsigned*)&h2; bh.w = *(unsigned*)&h3;
        *(uint4*)(g_B + (size_t)n * 32 + co * 4) = bh;
    }
}

// ---------- mlp2, ONE graph: f32x2 GEMM, K=64, fp16 h input. block = 64 nodes ----------
#define XS2 66
__global__ void __launch_bounds__(256) k_mlp2_g(const float* __restrict__ W2,
                                                const float* __restrict__ b2,
                                                int gbase) {
    __shared__ float sWd[CH * CH];
    __shared__ float sWb[CH * CH];
    __shared__ float sX[CH * XS2];
    int tid = threadIdx.x;
    int base = blockIdx.x * 64;             // local

    {
        float4* d4 = (float4*)sWd; float4* b4 = (float4*)sWb;
        const float4* gt = (const float4*)W2;
        const float4* gb = (const float4*)(W2 + CH * CH);
        #pragma unroll
        for (int i = 0; i < 4; i++) {
            float4 wt = gt[tid + i * 256];
            float4 wb = gb[tid + i * 256];
            d4[tid + i * 256] = make_float4(wt.x - wb.x, wt.y - wb.y,
                                            wt.z - wb.z, wt.w - wb.w);
            b4[tid + i * 256] = wb;
        }
    }
    // stage h (fp16 -> fp32), k-major
    #pragma unroll
    for (int i = 0; i < 2; i++) {
        int idx = tid + i * 256;             // 0..511
        int nl = base + (idx >> 3);
        int j  = idx & 7;                    // 8-channel chunk
        if (nl < NN) {
            uint4 v = *(const uint4*)(g_h16 + (size_t)(gbase + nl) * 32 + 4 * j);
            int loc = idx >> 3;
            float2 f0 = __half22float2(*(__half2*)&v.x);
            float2 f1 = __half22float2(*(__half2*)&v.y);
            float2 f2 = __half22float2(*(__half2*)&v.z);
            float2 f3 = __half22float2(*(__half2*)&v.w);
            sX[(8 * j + 0) * XS2 + loc] = f0.x;
            sX[(8 * j + 1) * XS2 + loc] = f0.y;
            sX[(8 * j + 2) * XS2 + loc] = f1.x;
            sX[(8 * j + 3) * XS2 + loc] = f1.y;
            sX[(8 * j + 4) * XS2 + loc] = f2.x;
            sX[(8 * j + 5) * XS2 + loc] = f2.y;
            sX[(8 * j + 6) * XS2 + loc] = f3.x;
            sX[(8 * j + 7) * XS2 + loc] = f3.y;
        }
    }
    __syncthreads();

    int np = tid & 31;
    int co = tid >> 5;
    u64 a2[2][4], b2r[2][4];
    #pragma unroll
    for (int j = 0; j < 4; j++) {
        float2 bv = *(const float2*)(b2 + co * 8 + 2 * j);
        u64 bp = pack2(bv.x, bv.y);
        a2[0][j] = bp; a2[1][j] = bp;
        b2r[0][j] = 0ull; b2r[1][j] = 0ull;
    }

    #pragma unroll
    for (int k = 0; k < CH; k++) {
        float2 xv = *(const float2*)(sX + k * XS2 + np * 2);
        ulonglong2 wd0 = *(const ulonglong2*)(sWd + k * CH + co * 8);
        ulonglong2 wd1 = *(const ulonglong2*)(sWd + k * CH + co * 8 + 4);
        ulonglong2 wb0 = *(const ulonglong2*)(sWb + k * CH + co * 8);
        ulonglong2 wb1 = *(const ulonglong2*)(sWb + k * CH + co * 8 + 4);
        u64 wd[4] = {wd0.x, wd0.y, wd1.x, wd1.y};
        u64 wb[4] = {wb0.x, wb0.y, wb1.x, wb1.y};
        float xs[2] = {xv.x, xv.y};
        #pragma unroll
        for (int i = 0; i < 2; i++) {
            u64 xp = pack2(xs[i], xs[i]);
            #pragma unroll
            for (int j = 0; j < 4; j++) {
                a2[i][j]  = ffma2(xp, wd[j], a2[i][j]);
                b2r[i][j] = ffma2(xp, wb[j], b2r[i][j]);
            }
        }
    }

    #pragma unroll
    for (int i = 0; i < 2; i++) {
        int nl = base + np * 2 + i;
        if (nl >= NN) continue;
        int n = gbase + nl;
        float av[8], bv[8];
        #pragma unroll
        for (int j = 0; j < 4; j++) {
            unpack2(a2[i][j], av[2 * j], av[2 * j + 1]);
            unpack2(b2r[i][j], bv[2 * j], bv[2 * j + 1]);
        }
        *(float4*)(g_A + (size_t)n * CH + co * 8)     = make_float4(av[0], av[1], av[2], av[3]);
        *(float4*)(g_A + (size_t)n * CH + co * 8 + 4) = make_float4(av[4], av[5], av[6], av[7]);
        __half2 h0 = __floats2half2_rn(bv[0], bv[1]);
        __half2 h1 = __floats2half2_rn(bv[2], bv[3]);
        __half2 h2 = __floats2half2_rn(bv[4], bv[5]);
        __half2 h3 = __floats2half2_rn(bv[6], bv[7]);
        uint4 bh;
        bh.x = *(unsigned*)&h0; bh.y = *(unsigned*)&h1;
        bh.z = *(unsigned*)&h2; bh.w = *(unsigned*)&h3;
        *(uint4*)(g_B + (size_t)n * 32 + co * 4) = bh;
    }
}

// ---------- edge conv, ONE graph: warp per node, 16 edges/iter, clamped tail ----------
// out[n][c] = max(0, A[n][c] + max_e B[src_e][c])
// max is idempotent: duplicated edges (index clamp to cnt-1) don't change the result.
__device__ __forceinline__ void hmax4(__half2 m[4], uint4 v) {
    m[0] = __hmax2(m[0], *(__half2*)&v.x);
    m[1] = __hmax2(m[1], *(__half2*)&v.y);
    m[2] = __hmax2(m[2], *(__half2*)&v.z);
    m[3] = __hmax2(m[3], *(__half2*)&v.w);
}

__device__ __forceinline__ void conv_gather(int n, int sbase, int q, int sub, __half2 m[4]) {
    int cnt = g_cnt[n];
    if (cnt > CAP) cnt = CAP;
    const unsigned short* sp = g_src + (size_t)n * CAP;

    unsigned ninf = 0xFC00FC00u;
    m[0] = *(__half2*)&ninf; m[1] = m[0]; m[2] = m[0]; m[3] = m[0];

    int e = 0;
    // full 16-edge blocks: vector index load + 4 gathers in flight
    for (; e + 16 <= cnt; e += 16) {
        ushort4 s4 = *(const ushort4*)(sp + e + 4 * sub);
        uint4 v0 = *(const uint4*)(g_B + (size_t)(s4.x + sbase) * 32 + 4 * q);
        uint4 v1 = *(const uint4*)(g_B + (size_t)(s4.y + sbase) * 32 + 4 * q);
        uint4 v2 = *(const uint4*)(g_B + (size_t)(s4.z + sbase) * 32 + 4 * q);
        uint4 v3 = *(const uint4*)(g_B + (size_t)(s4.w + sbase) * 32 + 4 * q);
        hmax4(m, v0); hmax4(m, v1); hmax4(m, v2); hmax4(m, v3);
    }
    // single clamped partial block: same MLP as main loop (4 idx + 4 gathers in flight)
    if (e < cnt) {
        int cm1 = cnt - 1;
        int i0 = e + 4 * sub;
        int j0 = min(i0,     cm1);
        int j1 = min(i0 + 1, cm1);
        int j2 = min(i0 + 2, cm1);
        int j3 = min(i0 + 3, cm1);
        unsigned short s0 = sp[j0];
        unsigned short s1 = sp[j1];
        unsigned short s2 = sp[j2];
        unsigned short s3 = sp[j3];
        uint4 v0 = *(const uint4*)(g_B + (size_t)(s0 + sbase) * 32 + 4 * q);
        uint4 v1 = *(const uint4*)(g_B + (size_t)(s1 + sbase) * 32 + 4 * q);
        uint4 v2 = *(const uint4*)(g_B + (size_t)(s2 + sbase) * 32 + 4 * q);
        uint4 v3 = *(const uint4*)(g_B + (size_t)(s3 + sbase) * 32 + 4 * q);
        hmax4(m, v0); hmax4(m, v1); hmax4(m, v2); hmax4(m, v3);
    }
    #pragma unroll
    for (int d = 8; d <= 16; d <<= 1) {
        #pragma unroll
        for (int r = 0; r < 4; r++) {
            unsigned t = __shfl_xor_sync(0xffffffffu, *(unsigned*)&m[r], d);
            m[r] = __hmax2(m[r], *(__half2*)&t);
        }
    }
}

// layer-1 conv: writes h (fp16) to g_h16
__global__ void __launch_bounds__(256) k_conv_h_g(int gbase) {
    int nl = (blockIdx.x * blockDim.x + threadIdx.x) >> 5;
    if (nl >= NN) return;
    int lane = threadIdx.x & 31;
    int q = lane & 7, sub = lane >> 3;
    int n = gbase + nl;
    __half2 m[4];
    conv_gather(n, gbase, q, sub, m);
    if (sub == 0) {
        float4 a0 = *(const float4*)(g_A + (size_t)n * CH + 8 * q);
        float4 a1 = *(const float4*)(g_A + (size_t)n * CH + 8 * q + 4);
        float2 f0 = __half22float2(m[0]);
        float2 f1 = __half22float2(m[1]);
        float2 f2 = __half22float2(m[2]);
        float2 f3 = __half22float2(m[3]);
        __half2 h0 = __floats2half2_rn(fmaxf(0.f, a0.x + f0.x), fmaxf(0.f, a0.y + f0.y));
        __half2 h1 = __floats2half2_rn(fmaxf(0.f, a0.z + f1.x), fmaxf(0.f, a0.w + f1.y));
        __half2 h2 = __floats2half2_rn(fmaxf(0.f, a1.x + f2.x), fmaxf(0.f, a1.y + f2.y));
        __half2 h3 = __floats2half2_rn(fmaxf(0.f, a1.z + f3.x), fmaxf(0.f, a1.w + f3.y));
        uint4 hh;
        hh.x = *(unsigned*)&h0; hh.y = *(unsigned*)&h1;
        hh.z = *(unsigned*)&h2; hh.w = *(unsigned*)&h3;
        *(uint4*)(g_h16 + (size_t)n * 32 + 4 * q) = hh;
    }
}

// layer-2 conv: writes fp32 output
__global__ void __launch_bounds__(256) k_conv_out_g(float* __restrict__ out, int gbase) {
    int nl = (blockIdx.x * blockDim.x + threadIdx.x) >> 5;
    if (nl >= NN) return;
    int lane = threadIdx.x & 31;
    int q = lane & 7, sub = lane >> 3;
    int n = gbase + nl;
    __half2 m[4];
    conv_gather(n, gbase, q, sub, m);
    if (sub == 0) {
        float4 a0 = *(const float4*)(g_A + (size_t)n * CH + 8 * q);
        float4 a1 = *(const float4*)(g_A + (size_t)n * CH + 8 * q + 4);
        float2 f0 = __half22float2(m[0]);
        float2 f1 = __half22float2(m[1]);
        float2 f2 = __half22float2(m[2]);
        float2 f3 = __half22float2(m[3]);
        float4 r0, r1;
        r0.x = fmaxf(0.f, a0.x + f0.x); r0.y = fmaxf(0.f, a0.y + f0.y);
        r0.z = fmaxf(0.f, a0.z + f1.x); r0.w = fmaxf(0.f, a0.w + f1.y);
        r1.x = fmaxf(0.f, a1.x + f2.x); r1.y = fmaxf(0.f, a1.y + f2.y);
        r1.z = fmaxf(0.f, a1.z + f3.x); r1.w = fmaxf(0.f, a1.w + f3.y);
        *(float4*)(out + (size_t)n * CH + 8 * q)     = r0;
        *(float4*)(out + (size_t)n * CH + 8 * q + 4) = r1;
    }
}

extern "C" void kernel_launch(void* const* d_in, const int* in_sizes, int n_in,
                              void* d_out, int out_size) {
    const float* x1  = (const float*)d_in[0];
    const int*   ei1 = (const int*)d_in[1];    // int32 (JAX x64 disabled)
    const float* x2  = (const float*)d_in[2];
    const int*   ei2 = (const int*)d_in[3];
    const float* W1  = (const float*)d_in[4];
    const float* b1  = (const float*)d_in[5];
    // d_in[6] = prelu_a: unused — PReLU input is provably >= 0 (identity branch)
    const float* W2  = (const float*)d_in[7];
    const float* b2  = (const float*)d_in[8];
    float* out = (float*)d_out;

    const int TB = 256;
    const int gI  = (2 * NN + TB - 1) / TB;
    const int gE  = ((NE / 8) + TB - 1) / TB;     // 8 edges/thread, one graph
    const int gM1 = (NN + 127) / 128;
    const int gM2 = (NN + 63) / 64;
    const int gW  = (NN * 32 + TB - 1) / TB;

    static cudaStream_t sB = nullptr;
    static cudaEvent_t evFork = nullptr, evJoin = nullptr;
    if (!sB) {
        cudaStreamCreateWithFlags(&sB, cudaStreamNonBlocking);
        cudaEventCreateWithFlags(&evFork, cudaEventDisableTiming);
        cudaEventCreateWithFlags(&evJoin, cudaEventDisableTiming);
    }

    // shared init, then fork two fully-independent per-graph chains (R14 topology)
    k_zero<<<gI, TB>>>();
    cudaEventRecord(evFork, 0);
    cudaStreamWaitEvent(sB, evFork, 0);

    // chain A (graph 1) on default stream
    k_scatter_g<<<gE, TB>>>(ei1, 0);
    k_mlp1_g<<<gM1, TB>>>(x1, b1, W1, 0);
    k_conv_h_g<<<gW, TB>>>(0);
    k_mlp2_g<<<gM2, TB>>>(W2, b2, 0);
    k_conv_out_g<<<gW, TB>>>(out, 0);

    // chain B (graph 2) on side stream
    k_scatter_g<<<gE, TB, 0, sB>>>(ei2, NN);
    k_mlp1_g<<<gM1, TB, 0, sB>>>(x2, b1, W1, NN);
    k_conv_h_g<<<gW, TB, 0, sB>>>(NN);
    k_mlp2_g<<<gM2, TB, 0, sB>>>(W2, b2, NN);
    k_conv_out_g<<<gW, TB, 0, sB>>>(out, NN);

    // join
    cudaEventRecord(evJoin, sB);
    cudaStreamWaitEvent(0, evJoin, 0);
}